// round 13
// baseline (speedup 1.0000x reference)
#include <cuda_runtime.h>
#include <cuda_bf16.h>

#define D   64
#define G3  192
#define NPAD 50176          // 196 * 256
#define NBLK 196
#define EMAXSZ 800000

// ---------------- device scratch (no allocations allowed) ----------------
__device__ __align__(16) float g_h [NPAD * D];
__device__ __align__(16) float g_h2[NPAD * D];
__device__ __align__(16) float g_ah[NPAD * D];
__device__ __align__(16) __nv_bfloat16 g_CbH[3 * G3 * D];  // C^T hi  [layer][g][k]
__device__ __align__(16) __nv_bfloat16 g_CbL[3 * G3 * D];  // C^T lo
__device__ __align__(16) __nv_bfloat16 g_WbH[G3 * D];      // W_hh hi [g][k]
__device__ __align__(16) __nv_bfloat16 g_WbL[G3 * D];      // W_hh lo
__device__ int g_deg[NPAD];
__device__ int g_incl[NPAD];
__device__ int g_bsum[NBLK];
__device__ int g_boff[NBLK];
__device__ int g_off[NPAD + 1];
__device__ int g_cur[NPAD];
__device__ int g_ssrc[EMAXSZ];

// ---------------- node transform: h = relu(x @ Wnt^T + bnt) ----------------
__global__ void k_nt(const float* __restrict__ x, const float* __restrict__ Wnt,
                     const float* __restrict__ bnt, int n) {
    int idx = blockIdx.x * blockDim.x + threadIdx.x;
    if (idx >= n * D) return;
    int node = idx >> 6, d = idx & 63;
    float acc = bnt[d];
    const float* xr = x + node * 6;
    const float* wr = Wnt + d * 6;
#pragma unroll
    for (int k = 0; k < 6; k++) acc = fmaf(xr[k], wr[k], acc);
    g_h[idx] = fmaxf(acc, 0.f);
}

// ---------------- precompute C^T[g][k] = sum_j weight[i][k][j]*W_ih[g][j], bf16 split ----------------
__global__ void k_makeC(const float* __restrict__ wt, const float* __restrict__ Wih) {
    int idx = blockIdx.x * blockDim.x + threadIdx.x;
    if (idx >= 3 * G3 * D) return;
    int k = idx & 63;
    int g = (idx / D) % G3;
    int i = idx / (G3 * D);
    const float* wr = wt + i * D * D + k * D;
    const float* ir = Wih + g * D;
    float s = 0.f;
#pragma unroll 8
    for (int j = 0; j < D; j++) s = fmaf(wr[j], ir[j], s);
    __nv_bfloat16 hi = __float2bfloat16(s);
    __nv_bfloat16 lo = __float2bfloat16(s - __bfloat162float(hi));
    g_CbH[idx] = hi;
    g_CbL[idx] = lo;
}

// ---------------- split W_hh[g][k] into bf16 hi/lo ----------------
__global__ void k_splitW(const float* __restrict__ Whh) {
    int idx = blockIdx.x * blockDim.x + threadIdx.x;
    if (idx >= G3 * D) return;
    float v = Whh[idx];
    __nv_bfloat16 hi = __float2bfloat16(v);
    __nv_bfloat16 lo = __float2bfloat16(v - __bfloat162float(hi));
    g_WbH[idx] = hi;
    g_WbL[idx] = lo;
}

// ---------------- CSR build: histogram / parallel scan / scatter ----------------
__global__ void k_zero() {
    int i = blockIdx.x * blockDim.x + threadIdx.x;
    if (i < NPAD) g_deg[i] = 0;
}

__global__ void k_hist(const int* __restrict__ ei, int e, int n) {
    int i = blockIdx.x * blockDim.x + threadIdx.x;
    if (i < e) {
        int d = ei[e + i];
        if ((unsigned)d < (unsigned)n) atomicAdd(&g_deg[d], 1);
    }
}

__global__ __launch_bounds__(256) void k_scanA() {
    __shared__ int sh[256];
    int t = threadIdx.x;
    int i = blockIdx.x * 256 + t;
    int v = g_deg[i];
    sh[t] = v;
    __syncthreads();
#pragma unroll
    for (int ofs = 1; ofs < 256; ofs <<= 1) {
        int u = (t >= ofs) ? sh[t - ofs] : 0;
        __syncthreads();
        sh[t] += u;
        __syncthreads();
    }
    g_incl[i] = sh[t];
    if (t == 255) g_bsum[blockIdx.x] = sh[255];
}

__global__ __launch_bounds__(256) void k_scanB() {
    __shared__ int sh[256];
    int t = threadIdx.x;
    int v = (t < NBLK) ? g_bsum[t] : 0;
    sh[t] = v;
    __syncthreads();
#pragma unroll
    for (int ofs = 1; ofs < 256; ofs <<= 1) {
        int u = (t >= ofs) ? sh[t - ofs] : 0;
        __syncthreads();
        sh[t] += u;
        __syncthreads();
    }
    if (t < NBLK) g_boff[t] = sh[t] - v;   // exclusive
}

__global__ __launch_bounds__(256) void k_scanC(int e) {
    int i = blockIdx.x * 256 + threadIdx.x;
    int off = g_boff[blockIdx.x] + g_incl[i] - g_deg[i];
    g_off[i] = off;
    g_cur[i] = off;
    if (i == 0) g_off[NPAD] = e;
}

__global__ void k_scatter(const int* __restrict__ ei, int e, int n) {
    int i = blockIdx.x * blockDim.x + threadIdx.x;
    if (i < e) {
        int dnode = ei[e + i];
        int snode = ei[i];
        if ((unsigned)dnode < (unsigned)n && (unsigned)snode < (unsigned)n) {
            int pos = atomicAdd(&g_cur[dnode], 1);
            g_ssrc[pos] = snode;
        }
    }
}

// ---------------- pull-based aggregate (R4 baseline) ----------------
__global__ void k_agg(int hb, int n) {
    const float* __restrict__ hin = hb ? g_h2 : g_h;
    int w = (blockIdx.x * blockDim.x + threadIdx.x) >> 5;
    int lane = threadIdx.x & 31;
    if (w >= n) return;
    int beg = g_off[w], end = g_off[w + 1];
    const float2* h2 = (const float2*)hin;
    float ax = 0.f, ay = 0.f;
    for (int e0 = beg; e0 < end; e0 += 32) {
        int m = end - e0; if (m > 32) m = 32;
        int s = (lane < m) ? g_ssrc[e0 + lane] : 0;
#pragma unroll 4
        for (int j = 0; j < m; j++) {
            int sj = __shfl_sync(0xffffffffu, s, j);
            float2 v = __ldg(&h2[sj * 32 + lane]);
            ax += v.x; ay += v.y;
        }
    }
    float2 o; o.x = ax; o.y = ay;
    ((float2*)g_ah)[w * 32 + lane] = o;
}

// ---------------- tensor-core fused GRU ----------------
// Block 512 threads, tile M=64 x N=192 x K=64, both GEMMs (input side: ah@C^T^T,
// hidden side: h@Whh^T) via bf16-split mma.sync.m16n8k16 (3 products).
// Warp w: wm=w&3 (m16 rows), wn=w>>2 (16-col slice of each gate). 48 accums/thread.

#define BSTR 72   // smem row stride in bf16 (144B: conflict-free ldmatrix + LDS)

// bf16-element offsets inside dynamic smem
#define OBCH 0
#define OBCL 13824
#define OBWH 27648
#define OBWL 41472
#define OAH  55296
#define OAL  59904
#define OHH  64512
#define OHL  69120
#define SMEM_BYTES (73728 * 2)

#define LDSM4(r, addr) \
    asm volatile("ldmatrix.sync.aligned.m8n8.x4.shared.b16 {%0,%1,%2,%3}, [%4];" \
        : "=r"((r)[0]), "=r"((r)[1]), "=r"((r)[2]), "=r"((r)[3]) : "r"(addr))

#define MMA(d, a, b0_, b1_) \
    asm volatile("mma.sync.aligned.m16n8k16.row.col.f32.bf16.bf16.f32 " \
        "{%0,%1,%2,%3},{%4,%5,%6,%7},{%8,%9},{%0,%1,%2,%3};" \
        : "+f"((d)[0]), "+f"((d)[1]), "+f"((d)[2]), "+f"((d)[3]) \
        : "r"((a)[0]), "r"((a)[1]), "r"((a)[2]), "r"((a)[3]), "r"(b0_), "r"(b1_))

__device__ __forceinline__ unsigned bf2pack(float a, float b) {
    __nv_bfloat162 t = __floats2bfloat162_rn(a, b);
    return *(unsigned*)&t;
}

__global__ __launch_bounds__(512)
void k_gemm(int hb, int layer, float* __restrict__ outp,
            const float* __restrict__ bi, const float* __restrict__ bh, int n) {
    const float* __restrict__ hin = hb ? g_h2 : g_h;
    float* __restrict__ hout = outp ? outp : (hb ? g_h : g_h2);

    extern __shared__ __align__(16) char smraw[];
    __nv_bfloat16* sb = (__nv_bfloat16*)smraw;
    unsigned sbase = (unsigned)__cvta_generic_to_shared(smraw);

    int tid = threadIdx.x;
    int node0 = blockIdx.x << 6;

    // ---- stage B matrices (hi/lo x 2 sides), [n=192][k=64] -> stride BSTR ----
    {
        const unsigned* sCh = (const unsigned*)(g_CbH + layer * G3 * D);
        const unsigned* sCl = (const unsigned*)(g_CbL + layer * G3 * D);
        const unsigned* sWh = (const unsigned*)g_WbH;
        const unsigned* sWl = (const unsigned*)g_WbL;
        unsigned* dst = (unsigned*)sb;
#pragma unroll
        for (int it = 0; it < 12; it++) {
            int i = tid + (it << 9);            // 0..6143 (uint pairs)
            int nrow = i >> 5, kp = i & 31;
            int doff = nrow * (BSTR / 2) + kp;
            dst[(OBCH >> 1) + doff] = sCh[i];
            dst[(OBCL >> 1) + doff] = sCl[i];
            dst[(OBWH >> 1) + doff] = sWh[i];
            dst[(OBWL >> 1) + doff] = sWl[i];
        }
    }

    // ---- stage A tiles: 64 rows x 64 k, fp32 -> bf16 hi/lo ----
    {
        int row = tid >> 3, kq = (tid & 7) << 3;   // 8 floats per thread
        int node = node0 + row;
        float va[8], vh[8];
#pragma unroll
        for (int j = 0; j < 8; j++) { va[j] = 0.f; vh[j] = 0.f; }
        if (node < n) {
            const float4* A4 = (const float4*)(g_ah + node * D + kq);
            const float4* H4 = (const float4*)(hin + node * D + kq);
            float4 t0 = A4[0], t1 = A4[1];
            va[0]=t0.x; va[1]=t0.y; va[2]=t0.z; va[3]=t0.w;
            va[4]=t1.x; va[5]=t1.y; va[6]=t1.z; va[7]=t1.w;
            t0 = H4[0]; t1 = H4[1];
            vh[0]=t0.x; vh[1]=t0.y; vh[2]=t0.z; vh[3]=t0.w;
            vh[4]=t1.x; vh[5]=t1.y; vh[6]=t1.z; vh[7]=t1.w;
        }
        unsigned* dst = (unsigned*)sb;
        int base = row * (BSTR / 2) + (kq >> 1);
#pragma unroll
        for (int j = 0; j < 4; j++) {
            float a0 = va[2*j], a1 = va[2*j+1];
            float h0 = vh[2*j], h1 = vh[2*j+1];
            float a0h = __bfloat162float(__float2bfloat16(a0));
            float a1h = __bfloat162float(__float2bfloat16(a1));
            float h0h = __bfloat162float(__float2bfloat16(h0));
            float h1h = __bfloat162float(__float2bfloat16(h1));
            dst[(OAH >> 1) + base + j] = bf2pack(a0h, a1h);
            dst[(OAL >> 1) + base + j] = bf2pack(a0 - a0h, a1 - a1h);
            dst[(OHH >> 1) + base + j] = bf2pack(h0h, h1h);
            dst[(OHL >> 1) + base + j] = bf2pack(h0 - h0h, h1 - h1h);
        }
    }
    __syncthreads();

    // ---- fragment addresses ----
    int lane = tid & 31, w = tid >> 5;
    int wm = w & 3, wn = w >> 2;
    int lr = lane & 7, grp = lane >> 3;

    unsigned aoff = (unsigned)(((wm * 16 + lr + (grp & 1) * 8) * BSTR + (grp >> 1) * 8) * 2);
    unsigned adAH = sbase + OAH * 2 + aoff;
    unsigned adAL = sbase + OAL * 2 + aoff;
    unsigned adHH = sbase + OHH * 2 + aoff;
    unsigned adHL = sbase + OHL * 2 + aoff;

    unsigned boff = (unsigned)(((wn * 16 + lr + (grp >> 1) * 8) * BSTR + (grp & 1) * 8) * 2);
    unsigned bdCH = sbase + OBCH * 2 + boff;
    unsigned bdCL = sbase + OBCL * 2 + boff;
    unsigned bdWH = sbase + OBWH * 2 + boff;
    unsigned bdWL = sbase + OBWL * 2 + boff;

    float ci[24], ch[24];
#pragma unroll
    for (int i = 0; i < 24; i++) { ci[i] = 0.f; ch[i] = 0.f; }

#pragma unroll
    for (int ks = 0; ks < 4; ks++) {
        unsigned AH[4], AL[4], HH[4], HL[4];
        unsigned kso = ks * 32;                 // 16 bf16 = 32 bytes
        LDSM4(AH, adAH + kso); LDSM4(AL, adAL + kso);
        LDSM4(HH, adHH + kso); LDSM4(HL, adHL + kso);
#pragma unroll
        for (int g = 0; g < 3; g++) {
            unsigned gofs = (unsigned)(g * 64 * BSTR * 2) + kso;
            unsigned BH[4], BL[4], WH[4], WL[4];
            LDSM4(BH, bdCH + gofs); LDSM4(BL, bdCL + gofs);
            LDSM4(WH, bdWH + gofs); LDSM4(WL, bdWL + gofs);
            float* c0 = ci + g * 8; float* c1 = c0 + 4;
            MMA(c0, AH, BH[0], BH[1]); MMA(c0, AH, BL[0], BL[1]); MMA(c0, AL, BH[0], BH[1]);
            MMA(c1, AH, BH[2], BH[3]); MMA(c1, AH, BL[2], BL[3]); MMA(c1, AL, BH[2], BH[3]);
            float* d0 = ch + g * 8; float* d1 = d0 + 4;
            MMA(d0, HH, WH[0], WH[1]); MMA(d0, HH, WL[0], WL[1]); MMA(d0, HL, WH[0], WH[1]);
            MMA(d1, HH, WH[2], WH[3]); MMA(d1, HH, WL[2], WL[3]); MMA(d1, HL, WH[2], WH[3]);
        }
    }

    // ---- epilogue: GRU gates ----
    int r4 = lane >> 2, c4 = lane & 3;
#pragma unroll
    for (int nt = 0; nt < 2; nt++) {
#pragma unroll
        for (int e = 0; e < 4; e++) {
            int row_l = wm * 16 + r4 + ((e >> 1) << 3);
            int node = node0 + row_l;
            if (node < n) {
                int chn = wn * 16 + nt * 8 + (c4 << 1) + (e & 1);
                int idx = nt * 4 + e;
                float i0 = ci[idx], i1 = ci[8 + idx], i2 = ci[16 + idx];
                float h0 = ch[idx], h1 = ch[8 + idx], h2 = ch[16 + idx];
                float xr = i0 + __ldg(&bi[chn])       + h0 + __ldg(&bh[chn]);
                float xz = i1 + __ldg(&bi[chn + 64])  + h1 + __ldg(&bh[chn + 64]);
                float r = 1.f / (1.f + __expf(-xr));
                float z = 1.f / (1.f + __expf(-xz));
                float nn = tanhf(fmaf(r, h2 + __ldg(&bh[chn + 128]),
                                      i2 + __ldg(&bi[chn + 128])));
                float hp = __ldg(&hin[node * D + chn]);
                hout[node * D + chn] = (1.f - z) * nn + z * hp;
            }
        }
    }
}

// ---------------- launch ----------------
extern "C" void kernel_launch(void* const* d_in, const int* in_sizes, int n_in,
                              void* d_out, int out_size) {
    const float* x   = (const float*)d_in[0];
    const int*   ei  = (const int*)d_in[1];      // int32: src[0..e), dst[e..2e)
    const float* Wnt = (const float*)d_in[4];
    const float* bnt = (const float*)d_in[5];
    const float* wt  = (const float*)d_in[6];
    const float* Wih = (const float*)d_in[7];
    const float* Whh = (const float*)d_in[8];
    const float* bi  = (const float*)d_in[9];
    const float* bh  = (const float*)d_in[10];
    float* out = (float*)d_out;

    int n = in_sizes[0] / 6;   // 50000
    int e = in_sizes[1] / 2;   // 800000

    cudaFuncSetAttribute(k_gemm, cudaFuncAttributeMaxDynamicSharedMemorySize, SMEM_BYTES);

    k_nt     <<<(n * D + 255) / 256, 256>>>(x, Wnt, bnt, n);
    k_makeC  <<<(3 * G3 * D + 255) / 256, 256>>>(wt, Wih);
    k_splitW <<<(G3 * D + 255) / 256, 256>>>(Whh);
    k_zero   <<<NBLK, 256>>>();
    k_hist   <<<(e + 255) / 256, 256>>>(ei, e, n);
    k_scanA  <<<NBLK, 256>>>();
    k_scanB  <<<1, 256>>>();
    k_scanC  <<<NBLK, 256>>>(e);
    k_scatter<<<(e + 255) / 256, 256>>>(ei, e, n);

    int aggGrid  = (n + 7) / 8;      // one warp per node
    int gemmGrid = (n + 63) / 64;    // 64 nodes per block

    k_agg <<<aggGrid, 256>>>(0, n);
    k_gemm<<<gemmGrid, 512, SMEM_BYTES>>>(0, 0, nullptr, bi, bh, n);
    k_agg <<<aggGrid, 256>>>(1, n);
    k_gemm<<<gemmGrid, 512, SMEM_BYTES>>>(1, 1, nullptr, bi, bh, n);
    k_agg <<<aggGrid, 256>>>(0, n);
    k_gemm<<<gemmGrid, 512, SMEM_BYTES>>>(0, 2, out, bi, bh, n);
}

// round 14
// speedup vs baseline: 1.0193x; 1.0193x over previous
#include <cuda_runtime.h>
#include <cuda_bf16.h>

#define D   64
#define G3  192
#define NPAD 50176          // 196 * 256
#define NBLK 196
#define EMAXSZ 800000

// ---------------- device scratch (no allocations allowed) ----------------
__device__ __align__(16) float g_h [NPAD * D];
__device__ __align__(16) float g_h2[NPAD * D];
__device__ __align__(16) float g_ah[NPAD * D];
__device__ __align__(16) __nv_bfloat16 g_CbH[3 * G3 * D];  // C^T hi  [layer][g][k]
__device__ __align__(16) __nv_bfloat16 g_CbL[3 * G3 * D];  // C^T lo
__device__ __align__(16) __nv_bfloat16 g_WbH[G3 * D];      // W_hh hi [g][k]
__device__ __align__(16) __nv_bfloat16 g_WbL[G3 * D];      // W_hh lo
__device__ int g_deg[NPAD];
__device__ int g_incl[NPAD];
__device__ int g_bsum[NBLK];
__device__ int g_boff[NBLK];
__device__ int g_off[NPAD + 1];
__device__ int g_cur[NPAD];
__device__ int g_ssrc[EMAXSZ];

// ---------------- node transform: h = relu(x @ Wnt^T + bnt) ----------------
__global__ void k_nt(const float* __restrict__ x, const float* __restrict__ Wnt,
                     const float* __restrict__ bnt, int n) {
    int idx = blockIdx.x * blockDim.x + threadIdx.x;
    if (idx >= n * D) return;
    int node = idx >> 6, d = idx & 63;
    float acc = bnt[d];
    const float* xr = x + node * 6;
    const float* wr = Wnt + d * 6;
#pragma unroll
    for (int k = 0; k < 6; k++) acc = fmaf(xr[k], wr[k], acc);
    g_h[idx] = fmaxf(acc, 0.f);
}

// ---------------- precompute C^T[g][k] = sum_j weight[i][k][j]*W_ih[g][j], bf16 split ----------------
__global__ void k_makeC(const float* __restrict__ wt, const float* __restrict__ Wih) {
    int idx = blockIdx.x * blockDim.x + threadIdx.x;
    if (idx >= 3 * G3 * D) return;
    int k = idx & 63;
    int g = (idx / D) % G3;
    int i = idx / (G3 * D);
    const float* wr = wt + i * D * D + k * D;
    const float* ir = Wih + g * D;
    float s = 0.f;
#pragma unroll 8
    for (int j = 0; j < D; j++) s = fmaf(wr[j], ir[j], s);
    __nv_bfloat16 hi = __float2bfloat16(s);
    __nv_bfloat16 lo = __float2bfloat16(s - __bfloat162float(hi));
    g_CbH[idx] = hi;
    g_CbL[idx] = lo;
}

// ---------------- split W_hh[g][k] into bf16 hi/lo ----------------
__global__ void k_splitW(const float* __restrict__ Whh) {
    int idx = blockIdx.x * blockDim.x + threadIdx.x;
    if (idx >= G3 * D) return;
    float v = Whh[idx];
    __nv_bfloat16 hi = __float2bfloat16(v);
    __nv_bfloat16 lo = __float2bfloat16(v - __bfloat162float(hi));
    g_WbH[idx] = hi;
    g_WbL[idx] = lo;
}

// ---------------- CSR build: histogram / parallel scan / scatter ----------------
__global__ void k_zero() {
    int i = blockIdx.x * blockDim.x + threadIdx.x;
    if (i < NPAD) g_deg[i] = 0;
}

__global__ void k_hist(const int* __restrict__ ei, int e, int n) {
    int i = blockIdx.x * blockDim.x + threadIdx.x;
    if (i < e) {
        int d = ei[e + i];
        if ((unsigned)d < (unsigned)n) atomicAdd(&g_deg[d], 1);
    }
}

__global__ __launch_bounds__(256) void k_scanA() {
    __shared__ int sh[256];
    int t = threadIdx.x;
    int i = blockIdx.x * 256 + t;
    int v = g_deg[i];
    sh[t] = v;
    __syncthreads();
#pragma unroll
    for (int ofs = 1; ofs < 256; ofs <<= 1) {
        int u = (t >= ofs) ? sh[t - ofs] : 0;
        __syncthreads();
        sh[t] += u;
        __syncthreads();
    }
    g_incl[i] = sh[t];
    if (t == 255) g_bsum[blockIdx.x] = sh[255];
}

__global__ __launch_bounds__(256) void k_scanB() {
    __shared__ int sh[256];
    int t = threadIdx.x;
    int v = (t < NBLK) ? g_bsum[t] : 0;
    sh[t] = v;
    __syncthreads();
#pragma unroll
    for (int ofs = 1; ofs < 256; ofs <<= 1) {
        int u = (t >= ofs) ? sh[t - ofs] : 0;
        __syncthreads();
        sh[t] += u;
        __syncthreads();
    }
    if (t < NBLK) g_boff[t] = sh[t] - v;   // exclusive
}

__global__ __launch_bounds__(256) void k_scanC(int e) {
    int i = blockIdx.x * 256 + threadIdx.x;
    int off = g_boff[blockIdx.x] + g_incl[i] - g_deg[i];
    g_off[i] = off;
    g_cur[i] = off;
    if (i == 0) g_off[NPAD] = e;
}

__global__ void k_scatter(const int* __restrict__ ei, int e, int n) {
    int i = blockIdx.x * blockDim.x + threadIdx.x;
    if (i < e) {
        int dnode = ei[e + i];
        int snode = ei[i];
        if ((unsigned)dnode < (unsigned)n && (unsigned)snode < (unsigned)n) {
            int pos = atomicAdd(&g_cur[dnode], 1);
            g_ssrc[pos] = snode;
        }
    }
}

// ---------------- pull-based aggregate (R4 baseline) ----------------
__global__ void k_agg(int hb, int n) {
    const float* __restrict__ hin = hb ? g_h2 : g_h;
    int w = (blockIdx.x * blockDim.x + threadIdx.x) >> 5;
    int lane = threadIdx.x & 31;
    if (w >= n) return;
    int beg = g_off[w], end = g_off[w + 1];
    const float2* h2 = (const float2*)hin;
    float ax = 0.f, ay = 0.f;
    for (int e0 = beg; e0 < end; e0 += 32) {
        int m = end - e0; if (m > 32) m = 32;
        int s = (lane < m) ? g_ssrc[e0 + lane] : 0;
#pragma unroll 4
        for (int j = 0; j < m; j++) {
            int sj = __shfl_sync(0xffffffffu, s, j);
            float2 v = __ldg(&h2[sj * 32 + lane]);
            ax += v.x; ay += v.y;
        }
    }
    float2 o; o.x = ax; o.y = ay;
    ((float2*)g_ah)[w * 32 + lane] = o;
}

// ---------------- tensor-core fused GRU ----------------
// Block 512 threads, tile M=64 x N=192 x K=64, both GEMMs (input side: ah@C^T^T,
// hidden side: h@Whh^T) via bf16-split mma.sync.m16n8k16 (3 products).
// Warp w: wm=w&3 (m16 rows), wn=w>>2 (16-col slice of each gate). 48 accums/thread.

#define BSTR 72   // smem row stride in bf16 (144B: conflict-free ldmatrix + LDS)

// bf16-element offsets inside dynamic smem
#define OBCH 0
#define OBCL 13824
#define OBWH 27648
#define OBWL 41472
#define OAH  55296
#define OAL  59904
#define OHH  64512
#define OHL  69120
#define SMEM_BYTES (73728 * 2)

#define LDSM4(r, addr) \
    asm volatile("ldmatrix.sync.aligned.m8n8.x4.shared.b16 {%0,%1,%2,%3}, [%4];" \
        : "=r"((r)[0]), "=r"((r)[1]), "=r"((r)[2]), "=r"((r)[3]) : "r"(addr))

#define MMA(d, a, b0_, b1_) \
    asm volatile("mma.sync.aligned.m16n8k16.row.col.f32.bf16.bf16.f32 " \
        "{%0,%1,%2,%3},{%4,%5,%6,%7},{%8,%9},{%0,%1,%2,%3};" \
        : "+f"((d)[0]), "+f"((d)[1]), "+f"((d)[2]), "+f"((d)[3]) \
        : "r"((a)[0]), "r"((a)[1]), "r"((a)[2]), "r"((a)[3]), "r"(b0_), "r"(b1_))

__device__ __forceinline__ unsigned bf2pack(float a, float b) {
    __nv_bfloat162 t = __floats2bfloat162_rn(a, b);
    return *(unsigned*)&t;
}

__global__ __launch_bounds__(512)
void k_gemm(int hb, int layer, float* __restrict__ outp,
            const float* __restrict__ bi, const float* __restrict__ bh, int n) {
    const float* __restrict__ hin = hb ? g_h2 : g_h;
    float* __restrict__ hout = outp ? outp : (hb ? g_h : g_h2);

    extern __shared__ __align__(16) char smraw[];
    __nv_bfloat16* sb = (__nv_bfloat16*)smraw;
    unsigned sbase = (unsigned)__cvta_generic_to_shared(smraw);

    int tid = threadIdx.x;
    int node0 = blockIdx.x << 6;

    // ---- stage B matrices (hi/lo x 2 sides), [n=192][k=64] -> stride BSTR ----
    {
        const unsigned* sCh = (const unsigned*)(g_CbH + layer * G3 * D);
        const unsigned* sCl = (const unsigned*)(g_CbL + layer * G3 * D);
        const unsigned* sWh = (const unsigned*)g_WbH;
        const unsigned* sWl = (const unsigned*)g_WbL;
        unsigned* dst = (unsigned*)sb;
#pragma unroll
        for (int it = 0; it < 12; it++) {
            int i = tid + (it << 9);            // 0..6143 (uint pairs)
            int nrow = i >> 5, kp = i & 31;
            int doff = nrow * (BSTR / 2) + kp;
            dst[(OBCH >> 1) + doff] = sCh[i];
            dst[(OBCL >> 1) + doff] = sCl[i];
            dst[(OBWH >> 1) + doff] = sWh[i];
            dst[(OBWL >> 1) + doff] = sWl[i];
        }
    }

    // ---- stage A tiles: 64 rows x 64 k, fp32 -> bf16 hi/lo ----
    {
        int row = tid >> 3, kq = (tid & 7) << 3;   // 8 floats per thread
        int node = node0 + row;
        float va[8], vh[8];
#pragma unroll
        for (int j = 0; j < 8; j++) { va[j] = 0.f; vh[j] = 0.f; }
        if (node < n) {
            const float4* A4 = (const float4*)(g_ah + node * D + kq);
            const float4* H4 = (const float4*)(hin + node * D + kq);
            float4 t0 = A4[0], t1 = A4[1];
            va[0]=t0.x; va[1]=t0.y; va[2]=t0.z; va[3]=t0.w;
            va[4]=t1.x; va[5]=t1.y; va[6]=t1.z; va[7]=t1.w;
            t0 = H4[0]; t1 = H4[1];
            vh[0]=t0.x; vh[1]=t0.y; vh[2]=t0.z; vh[3]=t0.w;
            vh[4]=t1.x; vh[5]=t1.y; vh[6]=t1.z; vh[7]=t1.w;
        }
        unsigned* dst = (unsigned*)sb;
        int base = row * (BSTR / 2) + (kq >> 1);
#pragma unroll
        for (int j = 0; j < 4; j++) {
            float a0 = va[2*j], a1 = va[2*j+1];
            float h0 = vh[2*j], h1 = vh[2*j+1];
            float a0h = __bfloat162float(__float2bfloat16(a0));
            float a1h = __bfloat162float(__float2bfloat16(a1));
            float h0h = __bfloat162float(__float2bfloat16(h0));
            float h1h = __bfloat162float(__float2bfloat16(h1));
            dst[(OAH >> 1) + base + j] = bf2pack(a0h, a1h);
            dst[(OAL >> 1) + base + j] = bf2pack(a0 - a0h, a1 - a1h);
            dst[(OHH >> 1) + base + j] = bf2pack(h0h, h1h);
            dst[(OHL >> 1) + base + j] = bf2pack(h0 - h0h, h1 - h1h);
        }
    }
    __syncthreads();

    // ---- fragment addresses ----
    int lane = tid & 31, w = tid >> 5;
    int wm = w & 3, wn = w >> 2;
    int lr = lane & 7, grp = lane >> 3;

    unsigned aoff = (unsigned)(((wm * 16 + lr + (grp & 1) * 8) * BSTR + (grp >> 1) * 8) * 2);
    unsigned adAH = sbase + OAH * 2 + aoff;
    unsigned adAL = sbase + OAL * 2 + aoff;
    unsigned adHH = sbase + OHH * 2 + aoff;
    unsigned adHL = sbase + OHL * 2 + aoff;

    unsigned boff = (unsigned)(((wn * 16 + lr + (grp >> 1) * 8) * BSTR + (grp & 1) * 8) * 2);
    unsigned bdCH = sbase + OBCH * 2 + boff;
    unsigned bdCL = sbase + OBCL * 2 + boff;
    unsigned bdWH = sbase + OBWH * 2 + boff;
    unsigned bdWL = sbase + OBWL * 2 + boff;

    float ci[24], ch[24];
#pragma unroll
    for (int i = 0; i < 24; i++) { ci[i] = 0.f; ch[i] = 0.f; }

#pragma unroll
    for (int ks = 0; ks < 4; ks++) {
        unsigned AH[4], AL[4], HH[4], HL[4];
        unsigned kso = ks * 32;                 // 16 bf16 = 32 bytes
        LDSM4(AH, adAH + kso); LDSM4(AL, adAL + kso);
        LDSM4(HH, adHH + kso); LDSM4(HL, adHL + kso);
#pragma unroll
        for (int g = 0; g < 3; g++) {
            unsigned gofs = (unsigned)(g * 64 * BSTR * 2) + kso;
            unsigned BH[4], BL[4], WH[4], WL[4];
            LDSM4(BH, bdCH + gofs); LDSM4(BL, bdCL + gofs);
            LDSM4(WH, bdWH + gofs); LDSM4(WL, bdWL + gofs);
            float* c0 = ci + g * 8; float* c1 = c0 + 4;
            MMA(c0, AH, BH[0], BH[1]); MMA(c0, AH, BL[0], BL[1]); MMA(c0, AL, BH[0], BH[1]);
            MMA(c1, AH, BH[2], BH[3]); MMA(c1, AH, BL[2], BL[3]); MMA(c1, AL, BH[2], BH[3]);
            float* d0 = ch + g * 8; float* d1 = d0 + 4;
            MMA(d0, HH, WH[0], WH[1]); MMA(d0, HH, WL[0], WL[1]); MMA(d0, HL, WH[0], WH[1]);
            MMA(d1, HH, WH[2], WH[3]); MMA(d1, HH, WL[2], WL[3]); MMA(d1, HL, WH[2], WH[3]);
        }
    }

    // ---- epilogue: GRU gates ----
    int r4 = lane >> 2, c4 = lane & 3;
#pragma unroll
    for (int nt = 0; nt < 2; nt++) {
#pragma unroll
        for (int e = 0; e < 4; e++) {
            int row_l = wm * 16 + r4 + ((e >> 1) << 3);
            int node = node0 + row_l;
            if (node < n) {
                int chn = wn * 16 + nt * 8 + (c4 << 1) + (e & 1);
                int idx = nt * 4 + e;
                float i0 = ci[idx], i1 = ci[8 + idx], i2 = ci[16 + idx];
                float h0 = ch[idx], h1 = ch[8 + idx], h2 = ch[16 + idx];
                float xr = i0 + __ldg(&bi[chn])       + h0 + __ldg(&bh[chn]);
                float xz = i1 + __ldg(&bi[chn + 64])  + h1 + __ldg(&bh[chn + 64]);
                float r = 1.f / (1.f + __expf(-xr));
                float z = 1.f / (1.f + __expf(-xz));
                float nn = tanhf(fmaf(r, h2 + __ldg(&bh[chn + 128]),
                                      i2 + __ldg(&bi[chn + 128])));
                float hp = __ldg(&hin[node * D + chn]);
                hout[node * D + chn] = (1.f - z) * nn + z * hp;
            }
        }
    }
}

// ---------------- launch ----------------
extern "C" void kernel_launch(void* const* d_in, const int* in_sizes, int n_in,
                              void* d_out, int out_size) {
    const float* x   = (const float*)d_in[0];
    const int*   ei  = (const int*)d_in[1];      // int32: src[0..e), dst[e..2e)
    const float* Wnt = (const float*)d_in[4];
    const float* bnt = (const float*)d_in[5];
    const float* wt  = (const float*)d_in[6];
    const float* Wih = (const float*)d_in[7];
    const float* Whh = (const float*)d_in[8];
    const float* bi  = (const float*)d_in[9];
    const float* bh  = (const float*)d_in[10];
    float* out = (float*)d_out;

    int n = in_sizes[0] / 6;   // 50000
    int e = in_sizes[1] / 2;   // 800000

    cudaFuncSetAttribute(k_gemm, cudaFuncAttributeMaxDynamicSharedMemorySize, SMEM_BYTES);

    k_nt     <<<(n * D + 255) / 256, 256>>>(x, Wnt, bnt, n);
    k_makeC  <<<(3 * G3 * D + 255) / 256, 256>>>(wt, Wih);
    k_splitW <<<(G3 * D + 255) / 256, 256>>>(Whh);
    k_zero   <<<NBLK, 256>>>();
    k_hist   <<<(e + 255) / 256, 256>>>(ei, e, n);
    k_scanA  <<<NBLK, 256>>>();
    k_scanB  <<<1, 256>>>();
    k_scanC  <<<NBLK, 256>>>(e);
    k_scatter<<<(e + 255) / 256, 256>>>(ei, e, n);

    int aggGrid  = (n + 7) / 8;      // one warp per node
    int gemmGrid = (n + 63) / 64;    // 64 nodes per block

    k_agg <<<aggGrid, 256>>>(0, n);
    k_gemm<<<gemmGrid, 512, SMEM_BYTES>>>(0, 0, nullptr, bi, bh, n);
    k_agg <<<aggGrid, 256>>>(1, n);
    k_gemm<<<gemmGrid, 512, SMEM_BYTES>>>(1, 1, nullptr, bi, bh, n);
    k_agg <<<aggGrid, 256>>>(0, n);
    k_gemm<<<gemmGrid, 512, SMEM_BYTES>>>(0, 2, out, bi, bh, n);
}

// round 15
// speedup vs baseline: 1.0195x; 1.0001x over previous
#include <cuda_runtime.h>
#include <cuda_bf16.h>

#define D   64
#define G3  192
#define NPAD 50176          // 196 * 256
#define NBLK 196
#define EMAXSZ 800000

// ---------------- device scratch (no allocations allowed) ----------------
__device__ __align__(16) float g_h [NPAD * D];
__device__ __align__(16) float g_h2[NPAD * D];
__device__ __align__(16) float g_ah[NPAD * D];
__device__ __align__(16) __nv_bfloat16 g_CbH[3 * G3 * D];  // C^T hi  [layer][g][k]
__device__ __align__(16) __nv_bfloat16 g_CbL[3 * G3 * D];  // C^T lo
__device__ __align__(16) __nv_bfloat16 g_WbH[G3 * D];      // W_hh hi [g][k]
__device__ __align__(16) __nv_bfloat16 g_WbL[G3 * D];      // W_hh lo
__device__ int g_deg[NPAD];
__device__ int g_incl[NPAD];
__device__ int g_bsum[NBLK];
__device__ int g_boff[NBLK];
__device__ int g_off[NPAD + 1];
__device__ int g_cur[NPAD];
__device__ int g_ssrc[EMAXSZ];

// ---------------- node transform: h = relu(x @ Wnt^T + bnt) ----------------
__global__ void k_nt(const float* __restrict__ x, const float* __restrict__ Wnt,
                     const float* __restrict__ bnt, int n) {
    int idx = blockIdx.x * blockDim.x + threadIdx.x;
    if (idx >= n * D) return;
    int node = idx >> 6, d = idx & 63;
    float acc = bnt[d];
    const float* xr = x + node * 6;
    const float* wr = Wnt + d * 6;
#pragma unroll
    for (int k = 0; k < 6; k++) acc = fmaf(xr[k], wr[k], acc);
    g_h[idx] = fmaxf(acc, 0.f);
}

// ---------------- precompute C^T[g][k] = sum_j weight[i][k][j]*W_ih[g][j], bf16 split ----------------
__global__ void k_makeC(const float* __restrict__ wt, const float* __restrict__ Wih) {
    int idx = blockIdx.x * blockDim.x + threadIdx.x;
    if (idx >= 3 * G3 * D) return;
    int k = idx & 63;
    int g = (idx / D) % G3;
    int i = idx / (G3 * D);
    const float* wr = wt + i * D * D + k * D;
    const float* ir = Wih + g * D;
    float s = 0.f;
#pragma unroll 8
    for (int j = 0; j < D; j++) s = fmaf(wr[j], ir[j], s);
    __nv_bfloat16 hi = __float2bfloat16(s);
    __nv_bfloat16 lo = __float2bfloat16(s - __bfloat162float(hi));
    g_CbH[idx] = hi;
    g_CbL[idx] = lo;
}

// ---------------- split W_hh[g][k] into bf16 hi/lo ----------------
__global__ void k_splitW(const float* __restrict__ Whh) {
    int idx = blockIdx.x * blockDim.x + threadIdx.x;
    if (idx >= G3 * D) return;
    float v = Whh[idx];
    __nv_bfloat16 hi = __float2bfloat16(v);
    __nv_bfloat16 lo = __float2bfloat16(v - __bfloat162float(hi));
    g_WbH[idx] = hi;
    g_WbL[idx] = lo;
}

// ---------------- CSR build: histogram / parallel scan / scatter ----------------
__global__ void k_zero() {
    int i = blockIdx.x * blockDim.x + threadIdx.x;
    if (i < NPAD) g_deg[i] = 0;
}

__global__ void k_hist(const int* __restrict__ ei, int e, int n) {
    int i = blockIdx.x * blockDim.x + threadIdx.x;
    if (i < e) {
        int d = ei[e + i];
        if ((unsigned)d < (unsigned)n) atomicAdd(&g_deg[d], 1);
    }
}

__global__ __launch_bounds__(256) void k_scanA() {
    __shared__ int sh[256];
    int t = threadIdx.x;
    int i = blockIdx.x * 256 + t;
    int v = g_deg[i];
    sh[t] = v;
    __syncthreads();
#pragma unroll
    for (int ofs = 1; ofs < 256; ofs <<= 1) {
        int u = (t >= ofs) ? sh[t - ofs] : 0;
        __syncthreads();
        sh[t] += u;
        __syncthreads();
    }
    g_incl[i] = sh[t];
    if (t == 255) g_bsum[blockIdx.x] = sh[255];
}

__global__ __launch_bounds__(256) void k_scanB() {
    __shared__ int sh[256];
    int t = threadIdx.x;
    int v = (t < NBLK) ? g_bsum[t] : 0;
    sh[t] = v;
    __syncthreads();
#pragma unroll
    for (int ofs = 1; ofs < 256; ofs <<= 1) {
        int u = (t >= ofs) ? sh[t - ofs] : 0;
        __syncthreads();
        sh[t] += u;
        __syncthreads();
    }
    if (t < NBLK) g_boff[t] = sh[t] - v;   // exclusive
}

__global__ __launch_bounds__(256) void k_scanC(int e) {
    int i = blockIdx.x * 256 + threadIdx.x;
    int off = g_boff[blockIdx.x] + g_incl[i] - g_deg[i];
    g_off[i] = off;
    g_cur[i] = off;
    if (i == 0) g_off[NPAD] = e;
}

__global__ void k_scatter(const int* __restrict__ ei, int e, int n) {
    int i = blockIdx.x * blockDim.x + threadIdx.x;
    if (i < e) {
        int dnode = ei[e + i];
        int snode = ei[i];
        if ((unsigned)dnode < (unsigned)n && (unsigned)snode < (unsigned)n) {
            int pos = atomicAdd(&g_cur[dnode], 1);
            g_ssrc[pos] = snode;
        }
    }
}

// ---------------- pull-based aggregate (R4 baseline) ----------------
__global__ void k_agg(int hb, int n) {
    const float* __restrict__ hin = hb ? g_h2 : g_h;
    int w = (blockIdx.x * blockDim.x + threadIdx.x) >> 5;
    int lane = threadIdx.x & 31;
    if (w >= n) return;
    int beg = g_off[w], end = g_off[w + 1];
    const float2* h2 = (const float2*)hin;
    float ax = 0.f, ay = 0.f;
    for (int e0 = beg; e0 < end; e0 += 32) {
        int m = end - e0; if (m > 32) m = 32;
        int s = (lane < m) ? g_ssrc[e0 + lane] : 0;
#pragma unroll 4
        for (int j = 0; j < m; j++) {
            int sj = __shfl_sync(0xffffffffu, s, j);
            float2 v = __ldg(&h2[sj * 32 + lane]);
            ax += v.x; ay += v.y;
        }
    }
    float2 o; o.x = ax; o.y = ay;
    ((float2*)g_ah)[w * 32 + lane] = o;
}

// ---------------- tensor-core fused GRU ----------------
// Block 512 threads, tile M=64 x N=192 x K=64, both GEMMs (input side: ah@C^T^T,
// hidden side: h@Whh^T) via bf16-split mma.sync.m16n8k16 (3 products).
// Warp w: wm=w&3 (m16 rows), wn=w>>2 (16-col slice of each gate). 48 accums/thread.

#define BSTR 72   // smem row stride in bf16 (144B: conflict-free ldmatrix + LDS)

// bf16-element offsets inside dynamic smem
#define OBCH 0
#define OBCL 13824
#define OBWH 27648
#define OBWL 41472
#define OAH  55296
#define OAL  59904
#define OHH  64512
#define OHL  69120
#define SMEM_BYTES (73728 * 2)

#define LDSM4(r, addr) \
    asm volatile("ldmatrix.sync.aligned.m8n8.x4.shared.b16 {%0,%1,%2,%3}, [%4];" \
        : "=r"((r)[0]), "=r"((r)[1]), "=r"((r)[2]), "=r"((r)[3]) : "r"(addr))

#define MMA(d, a, b0_, b1_) \
    asm volatile("mma.sync.aligned.m16n8k16.row.col.f32.bf16.bf16.f32 " \
        "{%0,%1,%2,%3},{%4,%5,%6,%7},{%8,%9},{%0,%1,%2,%3};" \
        : "+f"((d)[0]), "+f"((d)[1]), "+f"((d)[2]), "+f"((d)[3]) \
        : "r"((a)[0]), "r"((a)[1]), "r"((a)[2]), "r"((a)[3]), "r"(b0_), "r"(b1_))

__device__ __forceinline__ unsigned bf2pack(float a, float b) {
    __nv_bfloat162 t = __floats2bfloat162_rn(a, b);
    return *(unsigned*)&t;
}

__global__ __launch_bounds__(512)
void k_gemm(int hb, int layer, float* __restrict__ outp,
            const float* __restrict__ bi, const float* __restrict__ bh, int n) {
    const float* __restrict__ hin = hb ? g_h2 : g_h;
    float* __restrict__ hout = outp ? outp : (hb ? g_h : g_h2);

    extern __shared__ __align__(16) char smraw[];
    __nv_bfloat16* sb = (__nv_bfloat16*)smraw;
    unsigned sbase = (unsigned)__cvta_generic_to_shared(smraw);

    int tid = threadIdx.x;
    int node0 = blockIdx.x << 6;

    // ---- stage B matrices (hi/lo x 2 sides), [n=192][k=64] -> stride BSTR ----
    {
        const unsigned* sCh = (const unsigned*)(g_CbH + layer * G3 * D);
        const unsigned* sCl = (const unsigned*)(g_CbL + layer * G3 * D);
        const unsigned* sWh = (const unsigned*)g_WbH;
        const unsigned* sWl = (const unsigned*)g_WbL;
        unsigned* dst = (unsigned*)sb;
#pragma unroll
        for (int it = 0; it < 12; it++) {
            int i = tid + (it << 9);            // 0..6143 (uint pairs)
            int nrow = i >> 5, kp = i & 31;
            int doff = nrow * (BSTR / 2) + kp;
            dst[(OBCH >> 1) + doff] = sCh[i];
            dst[(OBCL >> 1) + doff] = sCl[i];
            dst[(OBWH >> 1) + doff] = sWh[i];
            dst[(OBWL >> 1) + doff] = sWl[i];
        }
    }

    // ---- stage A tiles: 64 rows x 64 k, fp32 -> bf16 hi/lo ----
    {
        int row = tid >> 3, kq = (tid & 7) << 3;   // 8 floats per thread
        int node = node0 + row;
        float va[8], vh[8];
#pragma unroll
        for (int j = 0; j < 8; j++) { va[j] = 0.f; vh[j] = 0.f; }
        if (node < n) {
            const float4* A4 = (const float4*)(g_ah + node * D + kq);
            const float4* H4 = (const float4*)(hin + node * D + kq);
            float4 t0 = A4[0], t1 = A4[1];
            va[0]=t0.x; va[1]=t0.y; va[2]=t0.z; va[3]=t0.w;
            va[4]=t1.x; va[5]=t1.y; va[6]=t1.z; va[7]=t1.w;
            t0 = H4[0]; t1 = H4[1];
            vh[0]=t0.x; vh[1]=t0.y; vh[2]=t0.z; vh[3]=t0.w;
            vh[4]=t1.x; vh[5]=t1.y; vh[6]=t1.z; vh[7]=t1.w;
        }
        unsigned* dst = (unsigned*)sb;
        int base = row * (BSTR / 2) + (kq >> 1);
#pragma unroll
        for (int j = 0; j < 4; j++) {
            float a0 = va[2*j], a1 = va[2*j+1];
            float h0 = vh[2*j], h1 = vh[2*j+1];
            float a0h = __bfloat162float(__float2bfloat16(a0));
            float a1h = __bfloat162float(__float2bfloat16(a1));
            float h0h = __bfloat162float(__float2bfloat16(h0));
            float h1h = __bfloat162float(__float2bfloat16(h1));
            dst[(OAH >> 1) + base + j] = bf2pack(a0h, a1h);
            dst[(OAL >> 1) + base + j] = bf2pack(a0 - a0h, a1 - a1h);
            dst[(OHH >> 1) + base + j] = bf2pack(h0h, h1h);
            dst[(OHL >> 1) + base + j] = bf2pack(h0 - h0h, h1 - h1h);
        }
    }
    __syncthreads();

    // ---- fragment addresses ----
    int lane = tid & 31, w = tid >> 5;
    int wm = w & 3, wn = w >> 2;
    int lr = lane & 7, grp = lane >> 3;

    unsigned aoff = (unsigned)(((wm * 16 + lr + (grp & 1) * 8) * BSTR + (grp >> 1) * 8) * 2);
    unsigned adAH = sbase + OAH * 2 + aoff;
    unsigned adAL = sbase + OAL * 2 + aoff;
    unsigned adHH = sbase + OHH * 2 + aoff;
    unsigned adHL = sbase + OHL * 2 + aoff;

    unsigned boff = (unsigned)(((wn * 16 + lr + (grp >> 1) * 8) * BSTR + (grp & 1) * 8) * 2);
    unsigned bdCH = sbase + OBCH * 2 + boff;
    unsigned bdCL = sbase + OBCL * 2 + boff;
    unsigned bdWH = sbase + OBWH * 2 + boff;
    unsigned bdWL = sbase + OBWL * 2 + boff;

    float ci[24], ch[24];
#pragma unroll
    for (int i = 0; i < 24; i++) { ci[i] = 0.f; ch[i] = 0.f; }

#pragma unroll
    for (int ks = 0; ks < 4; ks++) {
        unsigned AH[4], AL[4], HH[4], HL[4];
        unsigned kso = ks * 32;                 // 16 bf16 = 32 bytes
        LDSM4(AH, adAH + kso); LDSM4(AL, adAL + kso);
        LDSM4(HH, adHH + kso); LDSM4(HL, adHL + kso);
#pragma unroll
        for (int g = 0; g < 3; g++) {
            unsigned gofs = (unsigned)(g * 64 * BSTR * 2) + kso;
            unsigned BH[4], BL[4], WH[4], WL[4];
            LDSM4(BH, bdCH + gofs); LDSM4(BL, bdCL + gofs);
            LDSM4(WH, bdWH + gofs); LDSM4(WL, bdWL + gofs);
            float* c0 = ci + g * 8; float* c1 = c0 + 4;
            MMA(c0, AH, BH[0], BH[1]); MMA(c0, AH, BL[0], BL[1]); MMA(c0, AL, BH[0], BH[1]);
            MMA(c1, AH, BH[2], BH[3]); MMA(c1, AH, BL[2], BL[3]); MMA(c1, AL, BH[2], BH[3]);
            float* d0 = ch + g * 8; float* d1 = d0 + 4;
            MMA(d0, HH, WH[0], WH[1]); MMA(d0, HH, WL[0], WL[1]); MMA(d0, HL, WH[0], WH[1]);
            MMA(d1, HH, WH[2], WH[3]); MMA(d1, HH, WL[2], WL[3]); MMA(d1, HL, WH[2], WH[3]);
        }
    }

    // ---- epilogue: GRU gates ----
    int r4 = lane >> 2, c4 = lane & 3;
#pragma unroll
    for (int nt = 0; nt < 2; nt++) {
#pragma unroll
        for (int e = 0; e < 4; e++) {
            int row_l = wm * 16 + r4 + ((e >> 1) << 3);
            int node = node0 + row_l;
            if (node < n) {
                int chn = wn * 16 + nt * 8 + (c4 << 1) + (e & 1);
                int idx = nt * 4 + e;
                float i0 = ci[idx], i1 = ci[8 + idx], i2 = ci[16 + idx];
                float h0 = ch[idx], h1 = ch[8 + idx], h2 = ch[16 + idx];
                float xr = i0 + __ldg(&bi[chn])       + h0 + __ldg(&bh[chn]);
                float xz = i1 + __ldg(&bi[chn + 64])  + h1 + __ldg(&bh[chn + 64]);
                float r = 1.f / (1.f + __expf(-xr));
                float z = 1.f / (1.f + __expf(-xz));
                float nn = tanhf(fmaf(r, h2 + __ldg(&bh[chn + 128]),
                                      i2 + __ldg(&bi[chn + 128])));
                float hp = __ldg(&hin[node * D + chn]);
                hout[node * D + chn] = (1.f - z) * nn + z * hp;
            }
        }
    }
}

// ---------------- launch ----------------
extern "C" void kernel_launch(void* const* d_in, const int* in_sizes, int n_in,
                              void* d_out, int out_size) {
    const float* x   = (const float*)d_in[0];
    const int*   ei  = (const int*)d_in[1];      // int32: src[0..e), dst[e..2e)
    const float* Wnt = (const float*)d_in[4];
    const float* bnt = (const float*)d_in[5];
    const float* wt  = (const float*)d_in[6];
    const float* Wih = (const float*)d_in[7];
    const float* Whh = (const float*)d_in[8];
    const float* bi  = (const float*)d_in[9];
    const float* bh  = (const float*)d_in[10];
    float* out = (float*)d_out;

    int n = in_sizes[0] / 6;   // 50000
    int e = in_sizes[1] / 2;   // 800000

    cudaFuncSetAttribute(k_gemm, cudaFuncAttributeMaxDynamicSharedMemorySize, SMEM_BYTES);

    k_nt     <<<(n * D + 255) / 256, 256>>>(x, Wnt, bnt, n);
    k_makeC  <<<(3 * G3 * D + 255) / 256, 256>>>(wt, Wih);
    k_splitW <<<(G3 * D + 255) / 256, 256>>>(Whh);
    k_zero   <<<NBLK, 256>>>();
    k_hist   <<<(e + 255) / 256, 256>>>(ei, e, n);
    k_scanA  <<<NBLK, 256>>>();
    k_scanB  <<<1, 256>>>();
    k_scanC  <<<NBLK, 256>>>(e);
    k_scatter<<<(e + 255) / 256, 256>>>(ei, e, n);

    int aggGrid  = (n + 7) / 8;      // one warp per node
    int gemmGrid = (n + 63) / 64;    // 64 nodes per block

    k_agg <<<aggGrid, 256>>>(0, n);
    k_gemm<<<gemmGrid, 512, SMEM_BYTES>>>(0, 0, nullptr, bi, bh, n);
    k_agg <<<aggGrid, 256>>>(1, n);
    k_gemm<<<gemmGrid, 512, SMEM_BYTES>>>(1, 1, nullptr, bi, bh, n);
    k_agg <<<aggGrid, 256>>>(0, n);
    k_gemm<<<gemmGrid, 512, SMEM_BYTES>>>(0, 2, out, bi, bh, n);
}